// round 16
// baseline (speedup 1.0000x reference)
#include <cuda_runtime.h>
#include <math.h>
#include <stdint.h>

// ---------------- scratch (allocation-free: __device__ globals) ----------------
__device__ float g_fv[16ull * 512 * 64 * 64];    // f(0-255)+v(256-511)
__device__ float g_out1[16ull * 256 * 64 * 64];  // clustered output
__device__ float g_wt1d[96 * 1024];              // Wt1 dup-pairs: [k][2*o] = [k][2*o+1] = W[o][k]
__device__ float g_wt3d[256 * 192];              // Wt3 dup-pairs: [k][2*o], o<96
__device__ float g_b1[512];                      // bf || bv

// ---------------- prep: transposed, pair-duplicated weights + bias concat ----------------
__global__ __launch_bounds__(256) void prep_weights(
    const float* __restrict__ Wf, const float* __restrict__ bf,
    const float* __restrict__ Wv, const float* __restrict__ bv,
    const float* __restrict__ Wp)
{
    int idx = blockIdx.x * 256 + threadIdx.x;
    if (idx < 96 * 512) {
        int k = idx >> 9, o = idx & 511;
        float w = (o < 256) ? Wf[o * 96 + k] : Wv[(o - 256) * 96 + k];
        g_wt1d[k * 1024 + 2 * o]     = w;
        g_wt1d[k * 1024 + 2 * o + 1] = w;
    } else if (idx < 96 * 512 + 512) {
        int o = idx - 96 * 512;
        g_b1[o] = (o < 256) ? bf[o] : bv[o - 256];
    } else if (idx < 96 * 512 + 512 + 256 * 96) {
        int j = idx - (96 * 512 + 512);
        int k = j / 96, o = j % 96;
        float w = Wp[o * 256 + k];
        g_wt3d[k * 192 + 2 * o]     = w;
        g_wt3d[k * 192 + 2 * o + 1] = w;
    }
}

// ---------------- cp.async helpers ----------------
__device__ __forceinline__ void cp16(uint32_t sdst, const float* gsrc) {
    asm volatile("cp.async.cg.shared.global [%0], [%1], 16;" :: "r"(sdst), "l"(gsrc));
}
__device__ __forceinline__ void cp_commit() {
    asm volatile("cp.async.commit_group;" ::: "memory");
}
__device__ __forceinline__ void cp_wait1() {
    asm volatile("cp.async.wait_group 1;" ::: "memory");
}
__device__ __forceinline__ void cp_wait0() {
    asm volatile("cp.async.wait_group 0;" ::: "memory");
}

// ---------------- SGEMM: BMx128x16 tile, FFMA2 with pre-duplicated A pairs ----------------
// BMX = NT/16*8 rows; each thread: rows tm*8..tm*8+7, cols tn*4 & 64+tn*4.
// C[z][o][p] = sum_k W[o][k] * X[z][k][p] + bias[o]
#define BKK 16
#define BN 128

template<int BMX, int NT>
__global__ __launch_bounds__(NT, (BMX == 64) ? 4 : 2) void gemm_conv(
    const float* __restrict__ WtD, const float* __restrict__ bias,
    const float* __restrict__ X, float* __restrict__ C,
    int K, int P, int AstrideDup, int O)
{
    extern __shared__ float dsm[];
    // As: 3 stages of [BKK][BMX*2] dup floats; Bs: 3 stages of [BKK][BN]
    float* Asm = dsm;
    float* Bsm = dsm + 3 * BKK * BMX * 2;

    const int z = blockIdx.z;
    X += (size_t)z * K * P;
    C += (size_t)z * O * P;
    const int m0 = blockIdx.y * BMX;
    const int n0 = blockIdx.x * BN;
    const int tid = threadIdx.x;
    const int tm = tid >> 4;   // 0..NT/16-1
    const int tn = tid & 15;

    uint32_t sA[3], sB[3];
#pragma unroll
    for (int s = 0; s < 3; s++) {
        sA[s] = (uint32_t)__cvta_generic_to_shared(Asm + s * BKK * BMX * 2);
        sB[s] = (uint32_t)__cvta_generic_to_shared(Bsm + s * BKK * BN);
    }

    const int nch = K / BKK;

    unsigned long long acc2[8][4];
#pragma unroll
    for (int i = 0; i < 8; i++)
#pragma unroll
        for (int j = 0; j < 4; j++) acc2[i][j] = 0ull;

    // per-chunk copy: A = 16 k-rows x (BMX/2) float4 = 4*NT chunks; B = 512 float4
    auto issue = [&](int chk, int s) {
        const int k0 = chk * BKK;
        constexpr int AF4 = BMX / 2;          // float4 per k-row (dup)
#pragma unroll
        for (int it = 0; it < 4; it++) {
            int idx = it * NT + tid;
            int row = idx / AF4;
            int c4  = idx % AF4;
            const float* src = WtD + (size_t)(k0 + row) * AstrideDup + m0 * 2 + c4 * 4;
            cp16(sA[s] + (uint32_t)((row * (BMX * 2) + c4 * 4) << 2), src);
        }
#pragma unroll
        for (int j = tid; j < 512; j += NT) {
            int row = j >> 5;
            int c4  = (j & 31);
            const float* src = X + (size_t)(k0 + row) * P + n0 + c4 * 4;
            cp16(sB[s] + (uint32_t)((row * BN + c4 * 4) << 2), src);
        }
        cp_commit();
    };

    issue(0, 0);
    if (nch > 1) issue(1, 1);

    for (int chk = 0; chk < nch; chk++) {
        if (chk + 1 < nch) cp_wait1(); else cp_wait0();
        __syncthreads();
        if (chk + 2 < nch) issue(chk + 2, (chk + 2) % 3);

        const float* As_ = Asm + (chk % 3) * BKK * BMX * 2;
        const float* Bs_ = Bsm + (chk % 3) * BKK * BN;
#pragma unroll
        for (int k = 0; k < BKK; k++) {
            const float* ak = As_ + k * (BMX * 2) + tm * 16;
            ulonglong2 aq0 = *reinterpret_cast<const ulonglong2*>(ak);
            ulonglong2 aq1 = *reinterpret_cast<const ulonglong2*>(ak + 4);
            ulonglong2 aq2 = *reinterpret_cast<const ulonglong2*>(ak + 8);
            ulonglong2 aq3 = *reinterpret_cast<const ulonglong2*>(ak + 12);
            const float* bk = Bs_ + k * BN;
            ulonglong2 bq0 = *reinterpret_cast<const ulonglong2*>(bk + tn * 4);
            ulonglong2 bq1 = *reinterpret_cast<const ulonglong2*>(bk + 64 + tn * 4);
            unsigned long long aa[8] = {aq0.x, aq0.y, aq1.x, aq1.y,
                                        aq2.x, aq2.y, aq3.x, aq3.y};
            unsigned long long bb[4] = {bq0.x, bq0.y, bq1.x, bq1.y};
#pragma unroll
            for (int i = 0; i < 8; i++)
#pragma unroll
                for (int j = 0; j < 4; j++) {
                    asm("fma.rn.f32x2 %0, %1, %2, %0;"
                        : "+l"(acc2[i][j]) : "l"(aa[i]), "l"(bb[j]));
                }
        }
        // NOTE: no second barrier — next iteration's top sync protects stage reuse.
    }

    // ---- epilogue: rows m0 + tm*8 + i (always valid by tiling), bias + store ----
#pragma unroll
    for (int i = 0; i < 8; i++) {
        int gr = m0 + tm * 8 + i;
        float bs_ = bias[gr];
        float c[8];
#pragma unroll
        for (int j = 0; j < 4; j++) {
            uint32_t lo, hi;
            asm("mov.b64 {%0, %1}, %2;" : "=r"(lo), "=r"(hi) : "l"(acc2[i][j]));
            c[j * 2 + 0] = __uint_as_float(lo);
            c[j * 2 + 1] = __uint_as_float(hi);
        }
        float4 v0, v1;
        v0.x = c[0] + bs_; v0.y = c[1] + bs_;
        v0.z = c[2] + bs_; v0.w = c[3] + bs_;
        v1.x = c[4] + bs_; v1.y = c[5] + bs_;
        v1.z = c[6] + bs_; v1.w = c[7] + bs_;
        *reinterpret_cast<float4*>(C + (size_t)gr * P + n0 + tn * 4) = v0;
        *reinterpret_cast<float4*>(C + (size_t)gr * P + n0 + 64 + tn * 4) = v1;
    }
}

// ---------------- cluster kernel: one 128-thread block per region ----------------
__global__ __launch_bounds__(128) void cluster_kernel(
    const float* __restrict__ fv, float* __restrict__ out1,
    const float* __restrict__ alpha_p, const float* __restrict__ beta_p)
{
    const int r  = blockIdx.x;
    const int f2 = r & 7;
    const int f1 = (r >> 3) & 7;
    const int e  = (r >> 6) & 7;
    const int b  = r >> 9;
    const float alpha = alpha_p[0];
    const float beta  = beta_p[0];

    __shared__ float fs[64][33];
    __shared__ float vs[64][33];
    __shared__ float cfn[4][32];
    __shared__ float vcs[4][32];
    __shared__ float aggs[4][32];
    __shared__ float pnorm_s[64];
    __shared__ float simv[64];
    __shared__ int   idxs[64];
    __shared__ float cnt[4];

    const int tid = threadIdx.x;

    const float* fb = fv + ((size_t)b * 512 + e * 32) * 4096 + (f1 * 8) * 64 + f2 * 8;
    const float* vb = fb + (size_t)256 * 4096;

    for (int i = tid; i < 512; i += 128) {
        int ch   = i >> 4;
        int rem  = i & 15;
        int row  = rem >> 1;
        int half = rem & 1;
        int off  = ch * 4096 + row * 64 + half * 4;
        float4 fval = *reinterpret_cast<const float4*>(fb + off);
        float4 vval = *reinterpret_cast<const float4*>(vb + off);
        int pt = row * 8 + half * 4;
        fs[pt + 0][ch] = fval.x; fs[pt + 1][ch] = fval.y;
        fs[pt + 2][ch] = fval.z; fs[pt + 3][ch] = fval.w;
        vs[pt + 0][ch] = vval.x; vs[pt + 1][ch] = vval.y;
        vs[pt + 2][ch] = vval.z; vs[pt + 3][ch] = vval.w;
    }
    if (tid < 4) cnt[tid] = 0.0f;
    __syncthreads();

    {
        int m = tid >> 5;
        int c = tid & 31;
        int wy = (m >> 1) * 4;
        int hx = (m & 1) * 4;
        float cf = -INFINITY, cv = -INFINITY;
#pragma unroll
        for (int dy = 0; dy < 4; dy++)
#pragma unroll
            for (int dx = 0; dx < 4; dx++) {
                int pt = (wy + dy) * 8 + (hx + dx);
                cf = fmaxf(cf, fs[pt][c]);
                cv = fmaxf(cv, vs[pt][c]);
            }
        vcs[m][c] = cv;
        float sq = cf * cf;
#pragma unroll
        for (int o = 16; o > 0; o >>= 1) sq += __shfl_xor_sync(0xffffffffu, sq, o);
        float nrm = fmaxf(sqrtf(sq), 1e-12f);
        cfn[m][c] = cf / nrm;
    }
    if (tid < 64) {
        float sq = 0.0f;
#pragma unroll
        for (int c = 0; c < 32; c++) { float t = fs[tid][c]; sq += t * t; }
        pnorm_s[tid] = fmaxf(sqrtf(sq), 1e-12f);
    }
    __syncthreads();

    if (tid < 64) {
        int n = tid;
        float inv = 1.0f / pnorm_s[n];
        float best = -INFINITY;
        int bi = 0;
#pragma unroll
        for (int m = 0; m < 4; m++) {
            float dot = 0.0f;
#pragma unroll
            for (int c = 0; c < 32; c++) dot += cfn[m][c] * fs[n][c];
            float cosv = dot * inv;
            float s = 1.0f / (1.0f + expf(-(beta + alpha * cosv)));
            if (s > best) { best = s; bi = m; }
        }
        simv[n] = best;
        idxs[n] = bi;
        atomicAdd(&cnt[bi], 1.0f);
    }
    __syncthreads();

    {
        int m = tid >> 5;
        int c = tid & 31;
        float s = vcs[m][c];
        for (int n = 0; n < 64; n++) {
            if (idxs[n] == m) s += vs[n][c] * simv[n];
        }
        aggs[m][c] = s / (cnt[m] + 1.0f);
    }
    __syncthreads();

    if (tid < 64) {
        int n = tid;
        int m = idxs[n];
        float s = simv[n];
#pragma unroll
        for (int c = 0; c < 32; c++) fs[n][c] = aggs[m][c] * s;
    }
    __syncthreads();

    float* ob = out1 + ((size_t)b * 256 + e * 32) * 4096 + (f1 * 8) * 64 + f2 * 8;
    for (int i = tid; i < 512; i += 128) {
        int ch   = i >> 4;
        int rem  = i & 15;
        int row  = rem >> 1;
        int half = rem & 1;
        int pt = row * 8 + half * 4;
        float4 v;
        v.x = fs[pt + 0][ch];
        v.y = fs[pt + 1][ch];
        v.z = fs[pt + 2][ch];
        v.w = fs[pt + 3][ch];
        *reinterpret_cast<float4*>(ob + ch * 4096 + row * 64 + half * 4) = v;
    }
}

// ---------------- launch ----------------
extern "C" void kernel_launch(void* const* d_in, const int* in_sizes, int n_in,
                              void* d_out, int out_size)
{
    const float* x  = (const float*)d_in[0];   // [16,96,64,64]
    const float* Wf = (const float*)d_in[1];   // [256,96]
    const float* bf = (const float*)d_in[2];   // [256]
    const float* Wv = (const float*)d_in[3];   // [256,96]
    const float* bv = (const float*)d_in[4];   // [256]
    const float* Wp = (const float*)d_in[5];   // [96,256]
    const float* bp = (const float*)d_in[6];   // [96]
    const float* sa = (const float*)d_in[7];   // [1]
    const float* sb = (const float*)d_in[8];   // [1]
    float* out = (float*)d_out;                // [16,96,64,64]

    float *fv_ptr, *out1_ptr, *wt1_ptr, *wt3_ptr, *b1_ptr;
    cudaGetSymbolAddress((void**)&fv_ptr,   g_fv);
    cudaGetSymbolAddress((void**)&out1_ptr, g_out1);
    cudaGetSymbolAddress((void**)&wt1_ptr,  g_wt1d);
    cudaGetSymbolAddress((void**)&wt3_ptr,  g_wt3d);
    cudaGetSymbolAddress((void**)&b1_ptr,   g_b1);

    // dynamic smem sizes: As 3*16*BMX*2 + Bs 3*16*128 floats
    const int smem1 = (3 * 16 * 64 * 2 + 3 * 16 * 128) * 4;    // 49152 B
    const int smem3 = (3 * 16 * 96 * 2 + 3 * 16 * 128) * 4;    // 61440 B
    cudaFuncSetAttribute(gemm_conv<64, 128>,
                         cudaFuncAttributeMaxDynamicSharedMemorySize, smem1);
    cudaFuncSetAttribute(gemm_conv<96, 192>,
                         cudaFuncAttributeMaxDynamicSharedMemorySize, smem3);

    // 0) prep: dup-pair weight transpose + bias concat
    prep_weights<<<(96 * 512 + 512 + 256 * 96 + 255) / 256, 256>>>(Wf, bf, Wv, bv, Wp);

    // 1) f & v convs fused: [512 x 4096] per image
    {
        dim3 grid(4096 / BN, 512 / 64, 16);
        gemm_conv<64, 128><<<grid, 128, smem1>>>(wt1_ptr, b1_ptr, x, fv_ptr,
                                                 96, 4096, 1024, 512);
    }
    // 2) cluster stage: 8192 regions
    cluster_kernel<<<8192, 128>>>(fv_ptr, out1_ptr, sa, sb);
    // 3) final 1x1 conv: single 96-row tile, no dead rows
    {
        dim3 grid(4096 / BN, 1, 16);
        gemm_conv<96, 192><<<grid, 192, smem3>>>(wt3_ptr, bp, out1_ptr, out,
                                                 256, 4096, 192, 96);
    }
}

// round 17
// speedup vs baseline: 1.1021x; 1.1021x over previous
#include <cuda_runtime.h>
#include <math.h>
#include <stdint.h>

// ---------------- scratch (allocation-free: __device__ globals) ----------------
__device__ float g_fv[16ull * 512 * 64 * 64];    // f(0-255)+v(256-511)
__device__ float g_out1[16ull * 256 * 64 * 64];  // clustered output
__device__ float g_wt1[96 * 512];                // Wt1[k][o]: transposed Wf||Wv
__device__ float g_wt3[256 * 96];                // Wt3[k][o]: transposed Wp
__device__ float g_b1[512];                      // bf || bv

#define BKK 16
#define BN 128

// ---------------- prep: weight transpose + bias concat ----------------
__global__ __launch_bounds__(256) void prep_weights(
    const float* __restrict__ Wf, const float* __restrict__ bf,
    const float* __restrict__ Wv, const float* __restrict__ bv,
    const float* __restrict__ Wp)
{
    int idx = blockIdx.x * 256 + threadIdx.x;
    if (idx < 96 * 512) {
        int k = idx >> 9, o = idx & 511;
        g_wt1[idx] = (o < 256) ? Wf[o * 96 + k] : Wv[(o - 256) * 96 + k];
    } else if (idx < 96 * 512 + 512) {
        int o = idx - 96 * 512;
        g_b1[o] = (o < 256) ? bf[o] : bv[o - 256];
    } else if (idx < 96 * 512 + 512 + 256 * 96) {
        int j = idx - (96 * 512 + 512);
        int k = j / 96, o = j % 96;
        g_wt3[j] = Wp[o * 256 + k];
    }
}

// ---------------- cp.async helpers ----------------
__device__ __forceinline__ void cp16(uint32_t sdst, const float* gsrc) {
    asm volatile("cp.async.cg.shared.global [%0], [%1], 16;" :: "r"(sdst), "l"(gsrc));
}
__device__ __forceinline__ void cp_commit() {
    asm volatile("cp.async.commit_group;" ::: "memory");
}
__device__ __forceinline__ void cp_wait1() {
    asm volatile("cp.async.wait_group 1;" ::: "memory");
}
__device__ __forceinline__ void cp_wait0() {
    asm volatile("cp.async.wait_group 0;" ::: "memory");
}

// ---------------- SGEMM: BMXx128x16 tile, FFMA2 mov-packing, cp.async 3-stage ----------------
// NT threads; thread (tm,tn) computes rows {m0+tm*4..+3, m0+BMX/2+tm*4..+3},
// cols {n0+tn*4..+3, n0+64+tn*4..+3}.  C[z][o][p] = sum_k Wt[k][o]*X[z][k][p] + bias[o]
template<int BMX, int NT>
__global__ __launch_bounds__(NT, (BMX == 64) ? 4 : 2) void gemm_conv(
    const float* __restrict__ Wt, const float* __restrict__ bias,
    const float* __restrict__ X, float* __restrict__ C,
    int K, int P, int Ostride, int O)
{
    extern __shared__ float dsm[];
    float* Asm = dsm;                         // 3 stages of [BKK][BMX]
    float* Bsm = dsm + 3 * BKK * BMX;         // 3 stages of [BKK][BN]

    const int z = blockIdx.z;
    X += (size_t)z * K * P;
    C += (size_t)z * O * P;
    const int m0 = blockIdx.y * BMX;
    const int n0 = blockIdx.x * BN;
    const int tid = threadIdx.x;
    const int tm = tid >> 4;   // 0..NT/16-1
    const int tn = tid & 15;

    uint32_t sA[3], sB[3];
#pragma unroll
    for (int s = 0; s < 3; s++) {
        sA[s] = (uint32_t)__cvta_generic_to_shared(Asm + s * BKK * BMX);
        sB[s] = (uint32_t)__cvta_generic_to_shared(Bsm + s * BKK * BN);
    }

    const int nch = K / BKK;

    unsigned long long acc2[8][4];
#pragma unroll
    for (int i = 0; i < 8; i++)
#pragma unroll
        for (int j = 0; j < 4; j++) acc2[i][j] = 0ull;

    // per-chunk copies: A = BKK rows x BMX/4 float4 (2/thread); B = 512 float4
    auto issue = [&](int chk, int s) {
        const int k0 = chk * BKK;
        constexpr int AF4 = BMX / 4;
#pragma unroll
        for (int it = 0; it < 2; it++) {
            int idx = it * NT + tid;
            int row = idx / AF4;
            int c4  = idx % AF4;
            const float* src = Wt + (size_t)(k0 + row) * Ostride + m0 + c4 * 4;
            cp16(sA[s] + (uint32_t)((row * BMX + c4 * 4) << 2), src);
        }
        for (int j = tid; j < 512; j += NT) {
            int row = j >> 5;
            int c4  = (j & 31);
            const float* src = X + (size_t)(k0 + row) * P + n0 + c4 * 4;
            cp16(sB[s] + (uint32_t)((row * BN + c4 * 4) << 2), src);
        }
        cp_commit();
    };

    issue(0, 0);
    if (nch > 1) issue(1, 1);

    for (int chk = 0; chk < nch; chk++) {
        if (chk + 1 < nch) cp_wait1(); else cp_wait0();
        __syncthreads();
        if (chk + 2 < nch) issue(chk + 2, (chk + 2) % 3);

        const float* As_ = Asm + (chk % 3) * BKK * BMX;
        const float* Bs_ = Bsm + (chk % 3) * BKK * BN;
#pragma unroll
        for (int k = 0; k < BKK; k++) {
            const float* ak = As_ + k * BMX;
            const float* bk = Bs_ + k * BN;
            float4 a0 = *reinterpret_cast<const float4*>(ak + tm * 4);
            float4 a1 = *reinterpret_cast<const float4*>(ak + BMX / 2 + tm * 4);
            ulonglong2 bq0 = *reinterpret_cast<const ulonglong2*>(bk + tn * 4);
            ulonglong2 bq1 = *reinterpret_cast<const ulonglong2*>(bk + 64 + tn * 4);
            unsigned long long bb[4] = {bq0.x, bq0.y, bq1.x, bq1.y};
            float av[8] = {a0.x, a0.y, a0.z, a0.w, a1.x, a1.y, a1.z, a1.w};
#pragma unroll
            for (int i = 0; i < 8; i++) {
                unsigned long long aa;
                asm("mov.b64 %0, {%1, %1};" : "=l"(aa) : "r"(__float_as_uint(av[i])));
#pragma unroll
                for (int j = 0; j < 4; j++) {
                    asm("fma.rn.f32x2 %0, %1, %2, %0;"
                        : "+l"(acc2[i][j]) : "l"(aa), "l"(bb[j]));
                }
            }
        }
        // single barrier per chunk: next iteration's top sync orders stage reuse
    }

    // ---- epilogue: rows m0 + half*(BMX/2) + tm*4 + i (always valid), bias + store ----
#pragma unroll
    for (int half = 0; half < 2; half++) {
#pragma unroll
        for (int i = 0; i < 4; i++) {
            int gr = m0 + half * (BMX / 2) + tm * 4 + i;
            float bs_ = bias[gr];
            int ai = half * 4 + i;
            float c[8];
#pragma unroll
            for (int j = 0; j < 4; j++) {
                uint32_t lo, hi;
                asm("mov.b64 {%0, %1}, %2;" : "=r"(lo), "=r"(hi) : "l"(acc2[ai][j]));
                c[j * 2 + 0] = __uint_as_float(lo);
                c[j * 2 + 1] = __uint_as_float(hi);
            }
            float4 v0, v1;
            v0.x = c[0] + bs_; v0.y = c[1] + bs_;
            v0.z = c[2] + bs_; v0.w = c[3] + bs_;
            v1.x = c[4] + bs_; v1.y = c[5] + bs_;
            v1.z = c[6] + bs_; v1.w = c[7] + bs_;
            *reinterpret_cast<float4*>(C + (size_t)gr * P + n0 + tn * 4) = v0;
            *reinterpret_cast<float4*>(C + (size_t)gr * P + n0 + 64 + tn * 4) = v1;
        }
    }
}

// ---------------- cluster kernel: one 128-thread block per region ----------------
__global__ __launch_bounds__(128) void cluster_kernel(
    const float* __restrict__ fv, float* __restrict__ out1,
    const float* __restrict__ alpha_p, const float* __restrict__ beta_p)
{
    const int r  = blockIdx.x;
    const int f2 = r & 7;
    const int f1 = (r >> 3) & 7;
    const int e  = (r >> 6) & 7;
    const int b  = r >> 9;
    const float alpha = alpha_p[0];
    const float beta  = beta_p[0];

    __shared__ float fs[64][33];
    __shared__ float vs[64][33];
    __shared__ float cfn[4][32];
    __shared__ float vcs[4][32];
    __shared__ float aggs[4][32];
    __shared__ float pnorm_s[64];
    __shared__ float simv[64];
    __shared__ int   idxs[64];
    __shared__ float cnt[4];

    const int tid = threadIdx.x;

    const float* fb = fv + ((size_t)b * 512 + e * 32) * 4096 + (f1 * 8) * 64 + f2 * 8;
    const float* vb = fb + (size_t)256 * 4096;

    for (int i = tid; i < 512; i += 128) {
        int ch   = i >> 4;
        int rem  = i & 15;
        int row  = rem >> 1;
        int half = rem & 1;
        int off  = ch * 4096 + row * 64 + half * 4;
        float4 fval = *reinterpret_cast<const float4*>(fb + off);
        float4 vval = *reinterpret_cast<const float4*>(vb + off);
        int pt = row * 8 + half * 4;
        fs[pt + 0][ch] = fval.x; fs[pt + 1][ch] = fval.y;
        fs[pt + 2][ch] = fval.z; fs[pt + 3][ch] = fval.w;
        vs[pt + 0][ch] = vval.x; vs[pt + 1][ch] = vval.y;
        vs[pt + 2][ch] = vval.z; vs[pt + 3][ch] = vval.w;
    }
    if (tid < 4) cnt[tid] = 0.0f;
    __syncthreads();

    {
        int m = tid >> 5;
        int c = tid & 31;
        int wy = (m >> 1) * 4;
        int hx = (m & 1) * 4;
        float cf = -INFINITY, cv = -INFINITY;
#pragma unroll
        for (int dy = 0; dy < 4; dy++)
#pragma unroll
            for (int dx = 0; dx < 4; dx++) {
                int pt = (wy + dy) * 8 + (hx + dx);
                cf = fmaxf(cf, fs[pt][c]);
                cv = fmaxf(cv, vs[pt][c]);
            }
        vcs[m][c] = cv;
        float sq = cf * cf;
#pragma unroll
        for (int o = 16; o > 0; o >>= 1) sq += __shfl_xor_sync(0xffffffffu, sq, o);
        float nrm = fmaxf(sqrtf(sq), 1e-12f);
        cfn[m][c] = cf / nrm;
    }
    if (tid < 64) {
        float sq = 0.0f;
#pragma unroll
        for (int c = 0; c < 32; c++) { float t = fs[tid][c]; sq += t * t; }
        pnorm_s[tid] = fmaxf(sqrtf(sq), 1e-12f);
    }
    __syncthreads();

    if (tid < 64) {
        int n = tid;
        float inv = 1.0f / pnorm_s[n];
        float best = -INFINITY;
        int bi = 0;
#pragma unroll
        for (int m = 0; m < 4; m++) {
            float dot = 0.0f;
#pragma unroll
            for (int c = 0; c < 32; c++) dot += cfn[m][c] * fs[n][c];
            float cosv = dot * inv;
            float s = 1.0f / (1.0f + expf(-(beta + alpha * cosv)));
            if (s > best) { best = s; bi = m; }
        }
        simv[n] = best;
        idxs[n] = bi;
        atomicAdd(&cnt[bi], 1.0f);
    }
    __syncthreads();

    {
        int m = tid >> 5;
        int c = tid & 31;
        float s = vcs[m][c];
        for (int n = 0; n < 64; n++) {
            if (idxs[n] == m) s += vs[n][c] * simv[n];
        }
        aggs[m][c] = s / (cnt[m] + 1.0f);
    }
    __syncthreads();

    if (tid < 64) {
        int n = tid;
        int m = idxs[n];
        float s = simv[n];
#pragma unroll
        for (int c = 0; c < 32; c++) fs[n][c] = aggs[m][c] * s;
    }
    __syncthreads();

    float* ob = out1 + ((size_t)b * 256 + e * 32) * 4096 + (f1 * 8) * 64 + f2 * 8;
    for (int i = tid; i < 512; i += 128) {
        int ch   = i >> 4;
        int rem  = i & 15;
        int row  = rem >> 1;
        int half = rem & 1;
        int pt = row * 8 + half * 4;
        float4 v;
        v.x = fs[pt + 0][ch];
        v.y = fs[pt + 1][ch];
        v.z = fs[pt + 2][ch];
        v.w = fs[pt + 3][ch];
        *reinterpret_cast<float4*>(ob + ch * 4096 + row * 64 + half * 4) = v;
    }
}

// ---------------- launch ----------------
extern "C" void kernel_launch(void* const* d_in, const int* in_sizes, int n_in,
                              void* d_out, int out_size)
{
    const float* x  = (const float*)d_in[0];   // [16,96,64,64]
    const float* Wf = (const float*)d_in[1];   // [256,96]
    const float* bf = (const float*)d_in[2];   // [256]
    const float* Wv = (const float*)d_in[3];   // [256,96]
    const float* bv = (const float*)d_in[4];   // [256]
    const float* Wp = (const float*)d_in[5];   // [96,256]
    const float* bp = (const float*)d_in[6];   // [96]
    const float* sa = (const float*)d_in[7];   // [1]
    const float* sb = (const float*)d_in[8];   // [1]
    float* out = (float*)d_out;                // [16,96,64,64]

    float *fv_ptr, *out1_ptr, *wt1_ptr, *wt3_ptr, *b1_ptr;
    cudaGetSymbolAddress((void**)&fv_ptr,   g_fv);
    cudaGetSymbolAddress((void**)&out1_ptr, g_out1);
    cudaGetSymbolAddress((void**)&wt1_ptr,  g_wt1);
    cudaGetSymbolAddress((void**)&wt3_ptr,  g_wt3);
    cudaGetSymbolAddress((void**)&b1_ptr,   g_b1);

    const int smem1 = (3 * BKK * 64 + 3 * BKK * BN) * 4;    // 36864 B
    const int smem3 = (3 * BKK * 96 + 3 * BKK * BN) * 4;    // 43008 B
    cudaFuncSetAttribute(gemm_conv<64, 128>,
                         cudaFuncAttributeMaxDynamicSharedMemorySize, smem1);
    cudaFuncSetAttribute(gemm_conv<96, 192>,
                         cudaFuncAttributeMaxDynamicSharedMemorySize, smem3);

    // 0) prep: transpose weights, concat bias
    prep_weights<<<(96 * 512 + 512 + 256 * 96 + 255) / 256, 256>>>(Wf, bf, Wv, bv, Wp);

    // 1) f & v convs fused: [512 x 4096] per image
    {
        dim3 grid(4096 / BN, 512 / 64, 16);
        gemm_conv<64, 128><<<grid, 128, smem1>>>(wt1_ptr, b1_ptr, x, fv_ptr,
                                                 96, 4096, 512, 512);
    }
    // 2) cluster stage: 8192 regions
    cluster_kernel<<<8192, 128>>>(fv_ptr, out1_ptr, sa, sb);
    // 3) final 1x1 conv: single 96-row tile, no dead rows, B read once
    {
        dim3 grid(4096 / BN, 1, 16);
        gemm_conv<96, 192><<<grid, 192, smem3>>>(wt3_ptr, bp, out1_ptr, out,
                                                 256, 4096, 96, 96);
    }
}